// round 15
// baseline (speedup 1.0000x reference)
#include <cuda_runtime.h>
#include <cuda.h>
#include <cuda_fp16.h>
#include <math.h>
#include <stdint.h>

// ---------------------------------------------------------------------------
// Shapes: B=8192, I=512, H=1024, N=4096, K=1536
// gates = x@Wi + h@Wh + bh (bias in GEMM epilogue, fp32); per-gate LayerNorm;
// LSTM with tanh.approx. GEMM: fp16 mma.sync, fp32 accum, TMA + mbarrier ring.
// Warp tile 64x64 (4 warps/CTA) -> smem read duplication 2x instead of 4x.
// ---------------------------------------------------------------------------
#define B_DIM 8192
#define I_DIM 512
#define H_DIM 1024
#define N_DIM 4096
#define K_RAW 1536

__device__ __align__(1024) __half g_gates[(size_t)B_DIM * N_DIM];  // 64 MB
__device__ __align__(1024) __half g_Ah[(size_t)B_DIM * K_RAW];     // 25 MB
__device__ __align__(1024) __half g_Wh[(size_t)N_DIM * K_RAW];     // 12.5 MB
__device__ __align__(16) __half g_gamma_h[N_DIM];                  // 8 KB
__device__ __align__(16) __half g_beta_h[N_DIM];                   // 8 KB

// ------------------------------ PTX helpers --------------------------------
__device__ __forceinline__ uint32_t smem_u32(const void* p) {
    uint32_t a;
    asm("{ .reg .u64 t; cvta.to.shared.u64 t, %1; cvt.u32.u64 %0, t; }"
        : "=r"(a) : "l"(p));
    return a;
}

#define MBAR_INIT(addr, cnt) \
    asm volatile("mbarrier.init.shared.b64 [%0], %1;" :: "r"(addr), "r"(cnt) : "memory")

#define MBAR_EXPECT_TX(addr, bytes) \
    asm volatile("mbarrier.arrive.expect_tx.shared.b64 _, [%0], %1;" \
                 :: "r"(addr), "r"(bytes) : "memory")

#define MBAR_ARRIVE(addr) \
    asm volatile("mbarrier.arrive.shared.b64 _, [%0];" :: "r"(addr) : "memory")

#define FENCE_PROXY_ASYNC() \
    asm volatile("fence.proxy.async.shared::cta;" ::: "memory")

#define MBAR_WAIT(addr, parity) do {                                          \
    uint32_t _m = (addr), _p = (parity), _d;                                  \
    asm volatile("{\n\t.reg .pred p;\n\t"                                     \
        "mbarrier.try_wait.parity.acquire.cta.shared::cta.b64 p, [%1], %2;\n\t"\
        "selp.b32 %0, 1, 0, p;\n\t}"                                          \
        : "=r"(_d) : "r"(_m), "r"(_p) : "memory");                            \
    if (!_d) {                                                                \
        asm volatile("{\n\t.reg .pred P1;\n\t"                                \
            "W_%=:\n\t"                                                       \
            "mbarrier.try_wait.parity.acquire.cta.shared::cta.b64 P1, [%0], %1, 0x989680;\n\t" \
            "@P1 bra.uni D_%=;\n\t"                                           \
            "bra.uni W_%=;\n\t"                                               \
            "D_%=:\n\t}"                                                      \
            :: "r"(_m), "r"(_p) : "memory");                                  \
    }                                                                         \
} while (0)

__device__ __forceinline__ void tma_load_2d(uint32_t smem_addr, const void* map,
                                            int32_t cx, int32_t cy, uint32_t mbar) {
    asm volatile(
        "cp.async.bulk.tensor.2d.shared::cta.global.tile.mbarrier::complete_tx::bytes "
        "[%0], [%1, {%2, %3}], [%4];"
        :: "r"(smem_addr), "l"(map), "r"(cx), "r"(cy), "r"(mbar) : "memory");
}

#define LDSM_X4(r, addr)                                                      \
    asm volatile("ldmatrix.sync.aligned.m8n8.x4.shared.b16 {%0,%1,%2,%3}, [%4];" \
        : "=r"((r)[0]), "=r"((r)[1]), "=r"((r)[2]), "=r"((r)[3]) : "r"(addr))

#define MMA16816(d, a, b0, b1)                                                \
    asm volatile("mma.sync.aligned.m16n8k16.row.col.f32.f16.f16.f32 "         \
        "{%0,%1,%2,%3}, {%4,%5,%6,%7}, {%8,%9}, {%0,%1,%2,%3};"               \
        : "+f"((d)[0]), "+f"((d)[1]), "+f"((d)[2]), "+f"((d)[3])              \
        : "r"((a)[0]), "r"((a)[1]), "r"((a)[2]), "r"((a)[3]),                 \
          "r"(b0), "r"(b1))

__device__ __forceinline__ float tanhap(float x) {
    float y;
    asm("tanh.approx.f32 %0, %1;" : "=f"(y) : "f"(x));
    return y;
}
__device__ __forceinline__ float sigap(float x) {
    return fmaf(0.5f, tanhap(0.5f * x), 0.5f);
}

// ---------------------------------------------------------------------------
// Pack kernels.
// ---------------------------------------------------------------------------
__global__ __launch_bounds__(128)
void pack_a_kernel(const float* __restrict__ x, const float* __restrict__ h) {
    const int b  = blockIdx.y;
    const int k4 = (blockIdx.x * 128 + threadIdx.x) * 4;   // grid.x=3 -> 1536
    float4 v = (k4 < I_DIM)
        ? *(const float4*)&x[(size_t)b * I_DIM + k4]
        : *(const float4*)&h[(size_t)b * H_DIM + (k4 - I_DIM)];
    __half2 p0 = __floats2half2_rn(v.x, v.y);
    __half2 p1 = __floats2half2_rn(v.z, v.w);
    *(__half2*)&g_Ah[(size_t)b * K_RAW + k4]     = p0;
    *(__half2*)&g_Ah[(size_t)b * K_RAW + k4 + 2] = p1;
}

__global__ __launch_bounds__(256)
void pack_w_kernel(const float* __restrict__ Wi, const float* __restrict__ Wh) {
    __shared__ float t[32][33];
    const int k0 = blockIdx.x * 32;
    const int n0 = blockIdx.y * 32;
    const int tx = threadIdx.x, ty = threadIdx.y; // 32 x 8
#pragma unroll
    for (int i = 0; i < 4; ++i) {
        const int k = k0 + ty + i * 8;
        const int n = n0 + tx;
        float v = (k < I_DIM) ? Wi[(size_t)k * N_DIM + n]
                              : Wh[(size_t)(k - I_DIM) * N_DIM + n];
        t[ty + i * 8][tx] = v;
    }
    __syncthreads();
#pragma unroll
    for (int i = 0; i < 4; ++i) {
        const int n = n0 + ty + i * 8;
        const int k = k0 + tx;
        g_Wh[(size_t)n * K_RAW + k] = __float2half(t[tx][ty + i * 8]);
    }
}

__global__ __launch_bounds__(256)
void pack_const_kernel(const float* __restrict__ gamma,
                       const float* __restrict__ beta) {
    const int i = blockIdx.x * 256 + threadIdx.x;   // grid 16 -> 4096
    g_gamma_h[i] = __float2half(gamma[i]);
    g_beta_h[i]  = __float2half(beta[i]);
}

// ---------------------------------------------------------------------------
// fp16 TN GEMM: gates[M,N] = A_h[M,K] @ W_h[N,K]^T + bh   (fp16 output)
//   CTA 128x128x64, 128 thr, 4 warps (2m x 2n), warp tile 64x64.
//   3-stage TMA + mbarrier pipeline (SW128 swizzle), 2 CTAs/SM.
// ---------------------------------------------------------------------------
#define STAGES 3
#define BK 64
#define TILE_M 128
#define TILE_N 128
#define NK (K_RAW / BK)              // 24
#define STAGE_BYTES 32768            // A 16KB + B 16KB
#define STAGE_TX 32768u
#define SMEM_BYTES (1024 + 1024 + STAGES * STAGE_BYTES)

__global__ void __launch_bounds__(128, 2)
gemm_mma_kernel(const __grid_constant__ CUtensorMap tma_a,
                const __grid_constant__ CUtensorMap tma_w,
                const float* __restrict__ bh,
                __half* __restrict__ out) {
    extern __shared__ char smem[];
    const uint32_t s0 = (smem_u32(smem) + 1023u) & ~1023u;  // 1024-aligned

    const int tid  = threadIdx.x;
    const int wid  = tid >> 5;
    const int lane = tid & 31;
    const int warp_m = wid >> 1;     // 0..1  -> 64 rows
    const int warp_n = wid & 1;      // 0..1  -> 64 cols
    const int m0 = blockIdx.y * TILE_M;
    const int n0 = blockIdx.x * TILE_N;

    const uint32_t FULL0  = s0;            // full[s]  at s0 + s*16
    const uint32_t EMPTY0 = s0 + 8;        // empty[s] at s0 + s*16 + 8
    const uint32_t DATA0  = s0 + 1024;     // stage s at DATA0 + s*32768

    if (tid == 0) {
#pragma unroll
        for (int s = 0; s < STAGES; ++s) {
            MBAR_INIT(FULL0 + s * 16, 1);    // expect_tx arrival
            MBAR_INIT(EMPTY0 + s * 16, 4);   // one arrive per warp
        }
    }
    __syncthreads();

    // prologue: stages 0,1
    if (tid == 0) {
        FENCE_PROXY_ASYNC();
#pragma unroll
        for (int s = 0; s < STAGES - 1; ++s) {
            MBAR_EXPECT_TX(FULL0 + s * 16, STAGE_TX);
            tma_load_2d(DATA0 + s * STAGE_BYTES,         &tma_a, s * BK, m0,
                        FULL0 + s * 16);
            tma_load_2d(DATA0 + s * STAGE_BYTES + 16384, &tma_w, s * BK, n0,
                        FULL0 + s * 16);
        }
    }

    const int lrow  = (lane & 7) + ((lane >> 3) & 1) * 8;  // 0..15
    const int lhalf = lane >> 4;                           // 0/1 (k chunk)

    float acc[4][8][4];
#pragma unroll
    for (int i = 0; i < 4; ++i)
#pragma unroll
        for (int j = 0; j < 8; ++j)
#pragma unroll
            for (int e = 0; e < 4; ++e) acc[i][j][e] = 0.0f;

    int s_cur = 0, c_ph = 0;   // consumer cursor (full)
    int p_st = 0, p_ph = 0;    // producer cursor (empty), tid 0 only

    for (int kt = 0; kt < NK; ++kt) {
        const int knext = kt + STAGES - 1;
        if (tid == 0 && knext < NK) {
            const int s_nxt = (s_cur + STAGES - 1) % STAGES;
            if (kt >= 1) {
                MBAR_WAIT(EMPTY0 + p_st * 16, p_ph);   // all warps read slot
                FENCE_PROXY_ASYNC();                   // generic reads < async write
                if (++p_st == STAGES) { p_st = 0; p_ph ^= 1; }
            }
            MBAR_EXPECT_TX(FULL0 + s_nxt * 16, STAGE_TX);
            tma_load_2d(DATA0 + s_nxt * STAGE_BYTES,         &tma_a,
                        knext * BK, m0, FULL0 + s_nxt * 16);
            tma_load_2d(DATA0 + s_nxt * STAGE_BYTES + 16384, &tma_w,
                        knext * BK, n0, FULL0 + s_nxt * 16);
        }

        MBAR_WAIT(FULL0 + s_cur * 16, c_ph);

        const uint32_t sA = DATA0 + s_cur * STAGE_BYTES;
        const uint32_t sB = sA + 16384;

#pragma unroll
        for (int ks = 0; ks < 4; ++ks) {         // 4 x k16 per BK=64
            uint32_t a[4][4];
#pragma unroll
            for (int im = 0; im < 4; ++im) {
                const int row = warp_m * 64 + im * 16 + lrow;
                const int ch  = ks * 2 + lhalf;
                LDSM_X4(a[im], sA + row * 128 + ((ch ^ (row & 7)) << 4));
            }
            uint32_t b[4][4];
#pragma unroll
            for (int jb = 0; jb < 4; ++jb) {
                const int row = warp_n * 64 + jb * 16 + lrow;
                const int ch  = ks * 2 + lhalf;
                LDSM_X4(b[jb], sB + row * 128 + ((ch ^ (row & 7)) << 4));
            }
            if (ks == 3 && lane == 0) MBAR_ARRIVE(EMPTY0 + s_cur * 16);
#pragma unroll
            for (int im = 0; im < 4; ++im)
#pragma unroll
                for (int jn = 0; jn < 8; ++jn)
                    MMA16816(acc[im][jn], a[im],
                             b[jn >> 1][jn & 1], b[jn >> 1][(jn & 1) + 2]);
        }

        if (++s_cur == STAGES) { s_cur = 0; c_ph ^= 1; }
    }

    // epilogue: + bias (fp32), fp16 stores
    float2 bias[8];
#pragma unroll
    for (int jn = 0; jn < 8; ++jn) {
        const int col = n0 + warp_n * 64 + jn * 8 + (lane & 3) * 2;
        bias[jn] = *(const float2*)&bh[col];
    }
#pragma unroll
    for (int im = 0; im < 4; ++im) {
        const int r0 = m0 + warp_m * 64 + im * 16 + (lane >> 2);
#pragma unroll
        for (int jn = 0; jn < 8; ++jn) {
            const int col = n0 + warp_n * 64 + jn * 8 + (lane & 3) * 2;
            *(__half2*)&out[(size_t)r0 * N_DIM + col] =
                __floats2half2_rn(acc[im][jn][0] + bias[jn].x,
                                  acc[im][jn][1] + bias[jn].y);
            *(__half2*)&out[(size_t)(r0 + 8) * N_DIM + col] =
                __floats2half2_rn(acc[im][jn][2] + bias[jn].x,
                                  acc[im][jn][3] + bias[jn].y);
        }
    }
}

// ---------------------------------------------------------------------------
// LayerNorm + LSTM, register-resident (fp32 values, fp16 constants).
// ---------------------------------------------------------------------------
__global__ __launch_bounds__(128)
void ln_lstm_kernel(const __half* __restrict__ gates,  // [B, 4, H] fp16, biased
                    const float* __restrict__ c,       // [B, H]
                    float* __restrict__ h_new,
                    float* __restrict__ c_new) {
    const int b    = blockIdx.x;
    const int tid  = threadIdx.x;
    const int wrp  = tid >> 5;
    const int lane = tid & 31;
    const int j0   = tid * 8;

    __shared__ float rsum[4][4];   // [warp][gate]
    __shared__ float rsq [4][4];

    float v[4][8];
    float s[4], q[4];

#pragma unroll
    for (int g = 0; g < 4; ++g) {
        uint4 raw = *(const uint4*)(gates + (size_t)b * N_DIM + g * H_DIM + j0);
        float2 p0 = __half22float2(*(__half2*)&raw.x);
        float2 p1 = __half22float2(*(__half2*)&raw.y);
        float2 p2 = __half22float2(*(__half2*)&raw.z);
        float2 p3 = __half22float2(*(__half2*)&raw.w);
        v[g][0] = p0.x; v[g][1] = p0.y; v[g][2] = p1.x; v[g][3] = p1.y;
        v[g][4] = p2.x; v[g][5] = p2.y; v[g][6] = p3.x; v[g][7] = p3.y;
        float ss = 0.0f, qq = 0.0f;
#pragma unroll
        for (int i = 0; i < 8; ++i) { ss += v[g][i]; qq += v[g][i] * v[g][i]; }
        s[g] = ss; q[g] = qq;
    }

#pragma unroll
    for (int off = 16; off > 0; off >>= 1) {
#pragma unroll
        for (int g = 0; g < 4; ++g) {
            s[g] += __shfl_xor_sync(0xffffffffu, s[g], off);
            q[g] += __shfl_xor_sync(0xffffffffu, q[g], off);
        }
    }
    if (lane == 0) {
#pragma unroll
        for (int g = 0; g < 4; ++g) { rsum[wrp][g] = s[g]; rsq[wrp][g] = q[g]; }
    }
    __syncthreads();

    float mean[4], rstd[4];
    const float inv_n = 1.0f / (float)H_DIM;
#pragma unroll
    for (int g = 0; g < 4; ++g) {
        float ss = rsum[0][g] + rsum[1][g] + rsum[2][g] + rsum[3][g];
        float qq = rsq[0][g]  + rsq[1][g]  + rsq[2][g]  + rsq[3][g];
        mean[g] = ss * inv_n;
        float var = fmaxf(qq * inv_n - mean[g] * mean[g], 0.0f);
        rstd[g] = rsqrtf(var + 1e-5f);
    }

#pragma unroll
    for (int g = 0; g < 4; ++g) {
        uint4 graw = *(const uint4*)&g_gamma_h[g * H_DIM + j0];
        uint4 eraw = *(const uint4*)&g_beta_h[g * H_DIM + j0];
        const __half2* gh = (const __half2*)&graw;
        const __half2* eh = (const __half2*)&eraw;
        const float m = mean[g], r = rstd[g];
#pragma unroll
        for (int p = 0; p < 4; ++p) {
            float2 gm = __half22float2(gh[p]);
            float2 bt = __half22float2(eh[p]);
            v[g][2*p]   = (v[g][2*p]   - m) * r * gm.x + bt.x;
            v[g][2*p+1] = (v[g][2*p+1] - m) * r * gm.y + bt.y;
        }
    }

    const size_t base = (size_t)b * H_DIM + j0;
    float4 c0 = *(const float4*)&c[base];
    float4 c1 = *(const float4*)&c[base + 4];
    float cin[8] = {c0.x, c0.y, c0.z, c0.w, c1.x, c1.y, c1.z, c1.w};
    float cn[8], hn[8];
#pragma unroll
    for (int i = 0; i < 8; ++i) {
        cn[i] = sigap(v[1][i]) * cin[i] + sigap(v[0][i]) * tanhap(v[2][i]);
        hn[i] = sigap(v[3][i]) * tanhap(cn[i]);
    }
    *(float4*)&c_new[base]     = make_float4(cn[0], cn[1], cn[2], cn[3]);
    *(float4*)&c_new[base + 4] = make_float4(cn[4], cn[5], cn[6], cn[7]);
    *(float4*)&h_new[base]     = make_float4(hn[0], hn[1], hn[2], hn[3]);
    *(float4*)&h_new[base + 4] = make_float4(hn[4], hn[5], hn[6], hn[7]);
}

// ---------------------------------------------------------------------------
// Host launcher
// ---------------------------------------------------------------------------
typedef CUresult (*EncodeFn)(CUtensorMap*, CUtensorMapDataType, cuuint32_t, void*,
                             const cuuint64_t*, const cuuint64_t*, const cuuint32_t*,
                             const cuuint32_t*, CUtensorMapInterleave, CUtensorMapSwizzle,
                             CUtensorMapL2promotion, CUtensorMapFloatOOBfill);

static EncodeFn get_encode_fn() {
    static EncodeFn fn = nullptr;
    if (fn) return fn;
    void* p = nullptr;
    cudaDriverEntryPointQueryResult qr;
#if CUDART_VERSION >= 12050
    if (cudaGetDriverEntryPointByVersion("cuTensorMapEncodeTiled", &p, 12000,
                                         cudaEnableDefault, &qr) != cudaSuccess || !p)
#endif
    {
        p = nullptr;
        cudaGetDriverEntryPoint("cuTensorMapEncodeTiled", &p, cudaEnableDefault, &qr);
    }
    fn = (EncodeFn)p;
    return fn;
}

static void make_map(CUtensorMap* m, void* base, uint64_t rows) {
    cuuint64_t dims[2]    = {(cuuint64_t)K_RAW, (cuuint64_t)rows};
    cuuint64_t strides[1] = {(cuuint64_t)K_RAW * 2};
    cuuint32_t box[2]     = {BK, 128};   // 64 fp16 = 128B inner (SW128 limit)
    cuuint32_t estr[2]    = {1, 1};
    get_encode_fn()(m, CU_TENSOR_MAP_DATA_TYPE_BFLOAT16 /* 2-byte bit pattern */,
                    2, base, dims, strides, box, estr,
                    CU_TENSOR_MAP_INTERLEAVE_NONE, CU_TENSOR_MAP_SWIZZLE_128B,
                    CU_TENSOR_MAP_L2_PROMOTION_L2_128B, CU_TENSOR_MAP_FLOAT_OOB_FILL_NONE);
}

extern "C" void kernel_launch(void* const* d_in, const int* in_sizes, int n_in,
                              void* d_out, int out_size) {
    const float* x     = (const float*)d_in[0];
    const float* h     = (const float*)d_in[1];
    const float* c     = (const float*)d_in[2];
    const float* Wi    = (const float*)d_in[3];
    const float* Wh    = (const float*)d_in[4];
    const float* bh    = (const float*)d_in[5];
    const float* gamma = (const float*)d_in[6];
    const float* beta  = (const float*)d_in[7];

    float* out   = (float*)d_out;
    float* h_new = out;
    float* c_new = out + (size_t)B_DIM * H_DIM;

    __half* gates; cudaGetSymbolAddress((void**)&gates, g_gates);
    void* a_ptr;   cudaGetSymbolAddress(&a_ptr, g_Ah);
    void* w_ptr;   cudaGetSymbolAddress(&w_ptr, g_Wh);

    CUtensorMap tmA, tmW;
    make_map(&tmA, a_ptr, B_DIM);
    make_map(&tmW, w_ptr, N_DIM);

    pack_a_kernel<<<dim3(3, B_DIM), 128>>>(x, h);
    pack_w_kernel<<<dim3(K_RAW / 32, N_DIM / 32), dim3(32, 8)>>>(Wi, Wh);
    pack_const_kernel<<<N_DIM / 256, 256>>>(gamma, beta);

    cudaFuncSetAttribute(gemm_mma_kernel,
                         cudaFuncAttributeMaxDynamicSharedMemorySize, SMEM_BYTES);
    gemm_mma_kernel<<<dim3(N_DIM / TILE_N, B_DIM / TILE_M), 128, SMEM_BYTES>>>(
        tmA, tmW, bh, gates);

    ln_lstm_kernel<<<B_DIM, 128>>>(gates, c, h_new, c_new);
}

// round 16
// speedup vs baseline: 1.0251x; 1.0251x over previous
#include <cuda_runtime.h>
#include <cuda.h>
#include <cuda_fp16.h>
#include <math.h>
#include <stdint.h>

// ---------------------------------------------------------------------------
// Shapes: B=8192, I=512, H=1024, N=4096, K=1536
// gates = x@Wi + h@Wh + bh (bias in GEMM epilogue, fp32); per-gate LayerNorm;
// LSTM with tanh.approx. GEMM: fp16 mma.sync, fp32 accum, TMA + mbarrier ring
// (proven R13 config). ln_lstm: 2 rows / 256-thread block, register-resident.
// ---------------------------------------------------------------------------
#define B_DIM 8192
#define I_DIM 512
#define H_DIM 1024
#define N_DIM 4096
#define K_RAW 1536

__device__ __align__(1024) __half g_gates[(size_t)B_DIM * N_DIM];  // 64 MB
__device__ __align__(1024) __half g_Ah[(size_t)B_DIM * K_RAW];     // 25 MB
__device__ __align__(1024) __half g_Wh[(size_t)N_DIM * K_RAW];     // 12.5 MB
__device__ __align__(16) __half g_gamma_h[N_DIM];                  // 8 KB
__device__ __align__(16) __half g_beta_h[N_DIM];                   // 8 KB

// ------------------------------ PTX helpers --------------------------------
__device__ __forceinline__ uint32_t smem_u32(const void* p) {
    uint32_t a;
    asm("{ .reg .u64 t; cvta.to.shared.u64 t, %1; cvt.u32.u64 %0, t; }"
        : "=r"(a) : "l"(p));
    return a;
}

#define MBAR_INIT(addr, cnt) \
    asm volatile("mbarrier.init.shared.b64 [%0], %1;" :: "r"(addr), "r"(cnt) : "memory")

#define MBAR_EXPECT_TX(addr, bytes) \
    asm volatile("mbarrier.arrive.expect_tx.shared.b64 _, [%0], %1;" \
                 :: "r"(addr), "r"(bytes) : "memory")

#define MBAR_ARRIVE(addr) \
    asm volatile("mbarrier.arrive.shared.b64 _, [%0];" :: "r"(addr) : "memory")

#define FENCE_PROXY_ASYNC() \
    asm volatile("fence.proxy.async.shared::cta;" ::: "memory")

#define MBAR_WAIT(addr, parity) do {                                          \
    uint32_t _m = (addr), _p = (parity), _d;                                  \
    asm volatile("{\n\t.reg .pred p;\n\t"                                     \
        "mbarrier.try_wait.parity.acquire.cta.shared::cta.b64 p, [%1], %2;\n\t"\
        "selp.b32 %0, 1, 0, p;\n\t}"                                          \
        : "=r"(_d) : "r"(_m), "r"(_p) : "memory");                            \
    if (!_d) {                                                                \
        asm volatile("{\n\t.reg .pred P1;\n\t"                                \
            "W_%=:\n\t"                                                       \
            "mbarrier.try_wait.parity.acquire.cta.shared::cta.b64 P1, [%0], %1, 0x989680;\n\t" \
            "@P1 bra.uni D_%=;\n\t"                                           \
            "bra.uni W_%=;\n\t"                                               \
            "D_%=:\n\t}"                                                      \
            :: "r"(_m), "r"(_p) : "memory");                                  \
    }                                                                         \
} while (0)

__device__ __forceinline__ void tma_load_2d(uint32_t smem_addr, const void* map,
                                            int32_t cx, int32_t cy, uint32_t mbar) {
    asm volatile(
        "cp.async.bulk.tensor.2d.shared::cta.global.tile.mbarrier::complete_tx::bytes "
        "[%0], [%1, {%2, %3}], [%4];"
        :: "r"(smem_addr), "l"(map), "r"(cx), "r"(cy), "r"(mbar) : "memory");
}

#define LDSM_X4(r, addr)                                                      \
    asm volatile("ldmatrix.sync.aligned.m8n8.x4.shared.b16 {%0,%1,%2,%3}, [%4];" \
        : "=r"((r)[0]), "=r"((r)[1]), "=r"((r)[2]), "=r"((r)[3]) : "r"(addr))

#define MMA16816(d, a, b0, b1)                                                \
    asm volatile("mma.sync.aligned.m16n8k16.row.col.f32.f16.f16.f32 "         \
        "{%0,%1,%2,%3}, {%4,%5,%6,%7}, {%8,%9}, {%0,%1,%2,%3};"               \
        : "+f"((d)[0]), "+f"((d)[1]), "+f"((d)[2]), "+f"((d)[3])              \
        : "r"((a)[0]), "r"((a)[1]), "r"((a)[2]), "r"((a)[3]),                 \
          "r"(b0), "r"(b1))

__device__ __forceinline__ float tanhap(float x) {
    float y;
    asm("tanh.approx.f32 %0, %1;" : "=f"(y) : "f"(x));
    return y;
}
__device__ __forceinline__ float sigap(float x) {
    return fmaf(0.5f, tanhap(0.5f * x), 0.5f);
}

// ---------------------------------------------------------------------------
// Pack kernels.
// ---------------------------------------------------------------------------
__global__ __launch_bounds__(128)
void pack_a_kernel(const float* __restrict__ x, const float* __restrict__ h) {
    const int b  = blockIdx.y;
    const int k4 = (blockIdx.x * 128 + threadIdx.x) * 4;   // grid.x=3 -> 1536
    float4 v = (k4 < I_DIM)
        ? *(const float4*)&x[(size_t)b * I_DIM + k4]
        : *(const float4*)&h[(size_t)b * H_DIM + (k4 - I_DIM)];
    __half2 p0 = __floats2half2_rn(v.x, v.y);
    __half2 p1 = __floats2half2_rn(v.z, v.w);
    *(__half2*)&g_Ah[(size_t)b * K_RAW + k4]     = p0;
    *(__half2*)&g_Ah[(size_t)b * K_RAW + k4 + 2] = p1;
}

// Fused: blocks [0, 6144) transpose W; blocks [6144, 6160) pack gamma/beta.
__global__ __launch_bounds__(256)
void pack_wc_kernel(const float* __restrict__ Wi, const float* __restrict__ Wh,
                    const float* __restrict__ gamma, const float* __restrict__ beta) {
    if (blockIdx.x >= 6144) {
        const int i = (blockIdx.x - 6144) * 256 + threadIdx.x;  // 16 blocks -> 4096
        g_gamma_h[i] = __float2half(gamma[i]);
        g_beta_h[i]  = __float2half(beta[i]);
        return;
    }
    __shared__ float t[32][33];
    const int kb = blockIdx.x % 48;          // 48 k-blocks
    const int nb = blockIdx.x / 48;          // 128 n-blocks
    const int k0 = kb * 32;
    const int n0 = nb * 32;
    const int tx = threadIdx.x & 31, ty = threadIdx.x >> 5; // 32 x 8
#pragma unroll
    for (int i = 0; i < 4; ++i) {
        const int k = k0 + ty + i * 8;
        const int n = n0 + tx;
        float v = (k < I_DIM) ? Wi[(size_t)k * N_DIM + n]
                              : Wh[(size_t)(k - I_DIM) * N_DIM + n];
        t[ty + i * 8][tx] = v;
    }
    __syncthreads();
#pragma unroll
    for (int i = 0; i < 4; ++i) {
        const int n = n0 + ty + i * 8;
        const int k = k0 + tx;
        g_Wh[(size_t)n * K_RAW + k] = __float2half(t[tx][ty + i * 8]);
    }
}

// ---------------------------------------------------------------------------
// fp16 TN GEMM (R13 config, verbatim): gates = A_h @ W_h^T + bh (fp16 out)
//   CTA 128x128x64, 256 thr, 8 warps (2m x 4n), warp tile 64x32.
//   3-stage TMA + mbarrier pipeline (SW128 swizzle), 2 CTAs/SM.
// ---------------------------------------------------------------------------
#define STAGES 3
#define BK 64
#define TILE_M 128
#define TILE_N 128
#define NK (K_RAW / BK)              // 24
#define STAGE_BYTES 32768            // A 16KB + B 16KB
#define STAGE_TX 32768u
#define SMEM_BYTES (1024 + 1024 + STAGES * STAGE_BYTES)

__global__ void __launch_bounds__(256, 2)
gemm_mma_kernel(const __grid_constant__ CUtensorMap tma_a,
                const __grid_constant__ CUtensorMap tma_w,
                const float* __restrict__ bh,
                __half* __restrict__ out) {
    extern __shared__ char smem[];
    const uint32_t s0 = (smem_u32(smem) + 1023u) & ~1023u;  // 1024-aligned

    const int tid  = threadIdx.x;
    const int wid  = tid >> 5;
    const int lane = tid & 31;
    const int warp_m = wid >> 2;     // 0..1  -> 64 rows
    const int warp_n = wid & 3;      // 0..3  -> 32 cols
    const int m0 = blockIdx.y * TILE_M;
    const int n0 = blockIdx.x * TILE_N;

    const uint32_t FULL0  = s0;            // full[s]  at s0 + s*16
    const uint32_t EMPTY0 = s0 + 8;        // empty[s] at s0 + s*16 + 8
    const uint32_t DATA0  = s0 + 1024;     // stage s at DATA0 + s*32768

    if (tid == 0) {
#pragma unroll
        for (int s = 0; s < STAGES; ++s) {
            MBAR_INIT(FULL0 + s * 16, 1);    // expect_tx arrival
            MBAR_INIT(EMPTY0 + s * 16, 8);   // one arrive per warp
        }
    }
    __syncthreads();

    // prologue: stages 0,1
    if (tid == 0) {
        FENCE_PROXY_ASYNC();
#pragma unroll
        for (int s = 0; s < STAGES - 1; ++s) {
            MBAR_EXPECT_TX(FULL0 + s * 16, STAGE_TX);
            tma_load_2d(DATA0 + s * STAGE_BYTES,         &tma_a, s * BK, m0,
                        FULL0 + s * 16);
            tma_load_2d(DATA0 + s * STAGE_BYTES + 16384, &tma_w, s * BK, n0,
                        FULL0 + s * 16);
        }
    }

    const int lrow  = (lane & 7) + ((lane >> 3) & 1) * 8;  // 0..15
    const int lhalf = lane >> 4;                           // 0/1 (k chunk)

    float acc[4][4][4];
#pragma unroll
    for (int i = 0; i < 4; ++i)
#pragma unroll
        for (int j = 0; j < 4; ++j)
#pragma unroll
            for (int e = 0; e < 4; ++e) acc[i][j][e] = 0.0f;

    int s_cur = 0, c_ph = 0;   // consumer cursor (full)
    int p_st = 0, p_ph = 0;    // producer cursor (empty), tid 0 only

    for (int kt = 0; kt < NK; ++kt) {
        const int knext = kt + STAGES - 1;
        if (tid == 0 && knext < NK) {
            const int s_nxt = (s_cur + STAGES - 1) % STAGES;
            if (kt >= 1) {
                MBAR_WAIT(EMPTY0 + p_st * 16, p_ph);   // all warps read slot
                FENCE_PROXY_ASYNC();                   // generic reads < async write
                if (++p_st == STAGES) { p_st = 0; p_ph ^= 1; }
            }
            MBAR_EXPECT_TX(FULL0 + s_nxt * 16, STAGE_TX);
            tma_load_2d(DATA0 + s_nxt * STAGE_BYTES,         &tma_a,
                        knext * BK, m0, FULL0 + s_nxt * 16);
            tma_load_2d(DATA0 + s_nxt * STAGE_BYTES + 16384, &tma_w,
                        knext * BK, n0, FULL0 + s_nxt * 16);
        }

        MBAR_WAIT(FULL0 + s_cur * 16, c_ph);

        const uint32_t sA = DATA0 + s_cur * STAGE_BYTES;
        const uint32_t sB = sA + 16384;

#pragma unroll
        for (int ks = 0; ks < 4; ++ks) {         // 4 x k16 per BK=64
            uint32_t a[4][4];
#pragma unroll
            for (int im = 0; im < 4; ++im) {
                const int row = warp_m * 64 + im * 16 + lrow;
                const int ch  = ks * 2 + lhalf;
                LDSM_X4(a[im], sA + row * 128 + ((ch ^ (row & 7)) << 4));
            }
            uint32_t b[2][4];
#pragma unroll
            for (int jb = 0; jb < 2; ++jb) {
                const int row = warp_n * 32 + jb * 16 + lrow;
                const int ch  = ks * 2 + lhalf;
                LDSM_X4(b[jb], sB + row * 128 + ((ch ^ (row & 7)) << 4));
            }
#pragma unroll
            for (int im = 0; im < 4; ++im)
#pragma unroll
                for (int jn = 0; jn < 4; ++jn)
                    MMA16816(acc[im][jn], a[im],
                             b[jn >> 1][jn & 1], b[jn >> 1][(jn & 1) + 2]);
        }

        if (lane == 0) MBAR_ARRIVE(EMPTY0 + s_cur * 16);
        if (++s_cur == STAGES) { s_cur = 0; c_ph ^= 1; }
    }

    // epilogue: + bias (fp32), fp16 stores
    float2 bias[4];
#pragma unroll
    for (int jn = 0; jn < 4; ++jn) {
        const int col = n0 + warp_n * 32 + jn * 8 + (lane & 3) * 2;
        bias[jn] = *(const float2*)&bh[col];
    }
#pragma unroll
    for (int im = 0; im < 4; ++im) {
        const int r0 = m0 + warp_m * 64 + im * 16 + (lane >> 2);
#pragma unroll
        for (int jn = 0; jn < 4; ++jn) {
            const int col = n0 + warp_n * 32 + jn * 8 + (lane & 3) * 2;
            *(__half2*)&out[(size_t)r0 * N_DIM + col] =
                __floats2half2_rn(acc[im][jn][0] + bias[jn].x,
                                  acc[im][jn][1] + bias[jn].y);
            *(__half2*)&out[(size_t)(r0 + 8) * N_DIM + col] =
                __floats2half2_rn(acc[im][jn][2] + bias[jn].x,
                                  acc[im][jn][3] + bias[jn].y);
        }
    }
}

// ---------------------------------------------------------------------------
// LayerNorm + LSTM: 2 batch rows / 256-thread block, register-resident.
//   Threads [0,128): row 2b ; threads [128,256): row 2b+1.
// ---------------------------------------------------------------------------
__global__ __launch_bounds__(256)
void ln_lstm_kernel(const __half* __restrict__ gates,  // [B, 4, H] fp16, biased
                    const float* __restrict__ c,       // [B, H]
                    float* __restrict__ h_new,
                    float* __restrict__ c_new) {
    const int tid  = threadIdx.x;
    const int half = tid >> 7;                  // 0/1: row within pair
    const int t128 = tid & 127;
    const int wrp  = (tid >> 5) & 3;            // warp-within-half 0..3
    const int lane = tid & 31;
    const int b    = blockIdx.x * 2 + half;
    const int j0   = t128 * 8;

    __shared__ float rsum[2][4][4];   // [half][warp][gate]
    __shared__ float rsq [2][4][4];

    float v[4][8];
    float s[4], q[4];

#pragma unroll
    for (int g = 0; g < 4; ++g) {
        uint4 raw = *(const uint4*)(gates + (size_t)b * N_DIM + g * H_DIM + j0);
        float2 p0 = __half22float2(*(__half2*)&raw.x);
        float2 p1 = __half22float2(*(__half2*)&raw.y);
        float2 p2 = __half22float2(*(__half2*)&raw.z);
        float2 p3 = __half22float2(*(__half2*)&raw.w);
        v[g][0] = p0.x; v[g][1] = p0.y; v[g][2] = p1.x; v[g][3] = p1.y;
        v[g][4] = p2.x; v[g][5] = p2.y; v[g][6] = p3.x; v[g][7] = p3.y;
        float ss = 0.0f, qq = 0.0f;
#pragma unroll
        for (int i = 0; i < 8; ++i) { ss += v[g][i]; qq += v[g][i] * v[g][i]; }
        s[g] = ss; q[g] = qq;
    }

#pragma unroll
    for (int off = 16; off > 0; off >>= 1) {
#pragma unroll
        for (int g = 0; g < 4; ++g) {
            s[g] += __shfl_xor_sync(0xffffffffu, s[g], off);
            q[g] += __shfl_xor_sync(0xffffffffu, q[g], off);
        }
    }
    if (lane == 0) {
#pragma unroll
        for (int g = 0; g < 4; ++g) {
            rsum[half][wrp][g] = s[g];
            rsq [half][wrp][g] = q[g];
        }
    }
    __syncthreads();

    float mean[4], rstd[4];
    const float inv_n = 1.0f / (float)H_DIM;
#pragma unroll
    for (int g = 0; g < 4; ++g) {
        float ss = rsum[half][0][g] + rsum[half][1][g]
                 + rsum[half][2][g] + rsum[half][3][g];
        float qq = rsq[half][0][g] + rsq[half][1][g]
                 + rsq[half][2][g] + rsq[half][3][g];
        mean[g] = ss * inv_n;
        float var = fmaxf(qq * inv_n - mean[g] * mean[g], 0.0f);
        rstd[g] = rsqrtf(var + 1e-5f);
    }

#pragma unroll
    for (int g = 0; g < 4; ++g) {
        uint4 graw = *(const uint4*)&g_gamma_h[g * H_DIM + j0];
        uint4 eraw = *(const uint4*)&g_beta_h[g * H_DIM + j0];
        const __half2* gh = (const __half2*)&graw;
        const __half2* eh = (const __half2*)&eraw;
        const float m = mean[g], r = rstd[g];
#pragma unroll
        for (int p = 0; p < 4; ++p) {
            float2 gm = __half22float2(gh[p]);
            float2 bt = __half22float2(eh[p]);
            v[g][2*p]   = (v[g][2*p]   - m) * r * gm.x + bt.x;
            v[g][2*p+1] = (v[g][2*p+1] - m) * r * gm.y + bt.y;
        }
    }

    const size_t base = (size_t)b * H_DIM + j0;
    float4 c0 = *(const float4*)&c[base];
    float4 c1 = *(const float4*)&c[base + 4];
    float cin[8] = {c0.x, c0.y, c0.z, c0.w, c1.x, c1.y, c1.z, c1.w};
    float cn[8], hn[8];
#pragma unroll
    for (int i = 0; i < 8; ++i) {
        cn[i] = sigap(v[1][i]) * cin[i] + sigap(v[0][i]) * tanhap(v[2][i]);
        hn[i] = sigap(v[3][i]) * tanhap(cn[i]);
    }
    *(float4*)&c_new[base]     = make_float4(cn[0], cn[1], cn[2], cn[3]);
    *(float4*)&c_new[base + 4] = make_float4(cn[4], cn[5], cn[6], cn[7]);
    *(float4*)&h_new[base]     = make_float4(hn[0], hn[1], hn[2], hn[3]);
    *(float4*)&h_new[base + 4] = make_float4(hn[4], hn[5], hn[6], hn[7]);
}

// ---------------------------------------------------------------------------
// Host launcher
// ---------------------------------------------------------------------------
typedef CUresult (*EncodeFn)(CUtensorMap*, CUtensorMapDataType, cuuint32_t, void*,
                             const cuuint64_t*, const cuuint64_t*, const cuuint32_t*,
                             const cuuint32_t*, CUtensorMapInterleave, CUtensorMapSwizzle,
                             CUtensorMapL2promotion, CUtensorMapFloatOOBfill);

static EncodeFn get_encode_fn() {
    static EncodeFn fn = nullptr;
    if (fn) return fn;
    void* p = nullptr;
    cudaDriverEntryPointQueryResult qr;
#if CUDART_VERSION >= 12050
    if (cudaGetDriverEntryPointByVersion("cuTensorMapEncodeTiled", &p, 12000,
                                         cudaEnableDefault, &qr) != cudaSuccess || !p)
#endif
    {
        p = nullptr;
        cudaGetDriverEntryPoint("cuTensorMapEncodeTiled", &p, cudaEnableDefault, &qr);
    }
    fn = (EncodeFn)p;
    return fn;
}

static void make_map(CUtensorMap* m, void* base, uint64_t rows) {
    cuuint64_t dims[2]    = {(cuuint64_t)K_RAW, (cuuint64_t)rows};
    cuuint64_t strides[1] = {(cuuint64_t)K_RAW * 2};
    cuuint32_t box[2]     = {BK, 128};   // 64 fp16 = 128B inner (SW128 limit)
    cuuint32_t estr[2]    = {1, 1};
    get_encode_fn()(m, CU_TENSOR_MAP_DATA_TYPE_BFLOAT16 /* 2-byte bit pattern */,
                    2, base, dims, strides, box, estr,
                    CU_TENSOR_MAP_INTERLEAVE_NONE, CU_TENSOR_MAP_SWIZZLE_128B,
                    CU_TENSOR_MAP_L2_PROMOTION_L2_128B, CU_TENSOR_MAP_FLOAT_OOB_FILL_NONE);
}

extern "C" void kernel_launch(void* const* d_in, const int* in_sizes, int n_in,
                              void* d_out, int out_size) {
    const float* x     = (const float*)d_in[0];
    const float* h     = (const float*)d_in[1];
    const float* c     = (const float*)d_in[2];
    const float* Wi    = (const float*)d_in[3];
    const float* Wh    = (const float*)d_in[4];
    const float* bh    = (const float*)d_in[5];
    const float* gamma = (const float*)d_in[6];
    const float* beta  = (const float*)d_in[7];

    float* out   = (float*)d_out;
    float* h_new = out;
    float* c_new = out + (size_t)B_DIM * H_DIM;

    __half* gates; cudaGetSymbolAddress((void**)&gates, g_gates);
    void* a_ptr;   cudaGetSymbolAddress(&a_ptr, g_Ah);
    void* w_ptr;   cudaGetSymbolAddress(&w_ptr, g_Wh);

    CUtensorMap tmA, tmW;
    make_map(&tmA, a_ptr, B_DIM);
    make_map(&tmW, w_ptr, N_DIM);

    pack_a_kernel<<<dim3(3, B_DIM), 128>>>(x, h);
    pack_wc_kernel<<<6144 + 16, 256>>>(Wi, Wh, gamma, beta);

    cudaFuncSetAttribute(gemm_mma_kernel,
                         cudaFuncAttributeMaxDynamicSharedMemorySize, SMEM_BYTES);
    gemm_mma_kernel<<<dim3(N_DIM / TILE_N, B_DIM / TILE_M), 256, SMEM_BYTES>>>(
        tmA, tmW, bh, gates);

    ln_lstm_kernel<<<B_DIM / 2, 256>>>(gates, c, h_new, c_new);
}